// round 14
// baseline (speedup 1.0000x reference)
#include <cuda_runtime.h>
#include <cuda_bf16.h>
#include <cuda_fp16.h>
#include <math.h>
#include <stdint.h>

#define NB 16
#define CH 512
#define HW 1024
#define GUS_SMEM (65536 + 65536 + 4096)

// ---------------- scratch (static device globals) --------------------------
__device__ float g_ghat[32*32];
__device__ float g_s[NB*CH];
__device__ float g_ysc[NB*CH];
__device__ __half g_fT[(size_t)NB*HW*CH];
__device__ __nv_bfloat16 g_sigT[(size_t)NB*HW*CH];
__device__ float g_z[(size_t)NB*CH*HW];
__device__ __half g_A[(size_t)512*1024];
__device__ __half g_Bh[(size_t)NB*1024*1024];

// ---------------- PTX helpers ----------------------------------------------
__device__ __forceinline__ uint32_t smem_u32(const void* p) {
    uint32_t a;
    asm("{ .reg .u64 t; cvta.to.shared.u64 t, %1; cvt.u32.u64 %0, t; }" : "=r"(a) : "l"(p));
    return a;
}
__device__ __forceinline__ void cpasync16(uint32_t saddr, const void* gaddr) {
    asm volatile("cp.async.cg.shared.global [%0], [%1], 16;" :: "r"(saddr), "l"(gaddr) : "memory");
}
__device__ __forceinline__ void cp_commit() { asm volatile("cp.async.commit_group;" ::: "memory"); }
__device__ __forceinline__ void cp_wait1() { asm volatile("cp.async.wait_group 1;" ::: "memory"); }
__device__ __forceinline__ void cp_wait0() { asm volatile("cp.async.wait_group 0;" ::: "memory"); }
__device__ __forceinline__ uint32_t swz(uint32_t x) { return x ^ ((x >> 3) & 0x70); }
__device__ __forceinline__ float2 bf2f(uint32_t u) {
    __nv_bfloat162 h = *reinterpret_cast<__nv_bfloat162*>(&u);
    return __bfloat1622float2(h);
}
__device__ __forceinline__ float2 hf2f(uint32_t u) {
    __half2 h = *reinterpret_cast<__half2*>(&u);
    return __half22float2(h);
}

// ---------------- convA + ghat (merged) ------------------------------------
__global__ void k_pre(const float* __restrict__ Wd, const float* __restrict__ gus) {
    if (blockIdx.x < 512) {
        int r = blockIdx.x, c = threadIdx.x;
        g_A[(size_t)r*1024 + c] = __float2half_rn(Wd[(size_t)r*1024 + c]);
    } else {
        int t = threadIdx.x;
        int i = t >> 5, y = t & 31;
        const float* p = gus + (size_t)(i*32)*1024 + y*32;
        float s = 0.f;
        #pragma unroll
        for (int x = 0; x < 32; x++) s += p[x];
        g_ghat[t] = s;
    }
}

// ---------------- SE: spatial mean (float4) --------------------------------
__global__ void k_se_reduce(const float* __restrict__ x) {
    int c = blockIdx.x, b = blockIdx.y, t = threadIdx.x;
    const float4* p = (const float4*)(x + ((size_t)(b*CH + c))*HW);
    float s = 0.f;
    #pragma unroll
    for (int j = 0; j < 2; j++) {
        float4 v = p[t + j*128];
        s += v.x + v.y + v.z + v.w;
    }
    #pragma unroll
    for (int o = 16; o; o >>= 1) s += __shfl_xor_sync(~0u, s, o);
    __shared__ float ws[4];
    if ((t & 31) == 0) ws[t >> 5] = s;
    __syncthreads();
    if (t == 0) g_s[b*CH + c] = (ws[0]+ws[1]+ws[2]+ws[3]) * (1.0f/HW);
}

// ---------------- SE: tiny MLP ---------------------------------------------
__global__ void k_se_mlp(const float* __restrict__ w1, const float* __restrict__ b1,
                         const float* __restrict__ w2, const float* __restrict__ b2) {
    int b = blockIdx.x, t = threadIdx.x;
    __shared__ float ssh[CH];
    __shared__ float hsh[32];
    ssh[t] = g_s[b*CH + t];
    __syncthreads();
    if (t < 32) {
        float a = b1[t];
        const float* w = w1 + t*CH;
        for (int c = 0; c < CH; c++) a += w[c]*ssh[c];
        hsh[t] = fmaxf(a, 0.f);
    }
    __syncthreads();
    float a = b2[t];
    const float* w = w2 + t*32;
    #pragma unroll
    for (int j = 0; j < 32; j++) a += w[j]*hsh[j];
    g_ysc[b*CH + t] = 1.f/(1.f + __expf(-a));
}

// ---------------- out32 transpose + sigmoid (fT fp16, sigT bf16) -----------
__global__ void k_makeT(const float* __restrict__ x) {
    int p0 = blockIdx.x*32, c0 = blockIdx.y*32, b = blockIdx.z;
    int tx = threadIdx.x, ty = threadIdx.y;
    __shared__ float tile[32][33];
    #pragma unroll
    for (int i = 0; i < 4; i++) {
        int c = c0 + ty + i*8;
        tile[ty+i*8][tx] = x[((size_t)(b*CH + c))*HW + p0 + tx] * g_ysc[b*CH + c];
    }
    __syncthreads();
    #pragma unroll
    for (int i = 0; i < 4; i++) {
        int p = p0 + ty + i*8;
        float v = tile[tx][ty+i*8];
        size_t idx = ((size_t)(b*HW + p))*CH + c0 + tx;
        g_fT[idx] = __float2half_rn(v);
        g_sigT[idx] = __float2bfloat16(1.f/(1.f + __expf(-v)));
    }
}

// ---------------- fused gus: both separable stages, smem-resident ----------
// block = (cchunk 0..15, b). smem: fTs[1024][32] fp16 | W1s[32][32][32] fp16 | ghs[32][32] f32
// ghs[r*32+q] = ghat[q][r]  (serves both stages: A needs ghat[k][x], B needs ghat[i][y])
__global__ void __launch_bounds__(256) k_gus() {
    extern __shared__ char gsm[];
    __half* fTs = (__half*)gsm;                 // [p=1024][c=32]
    __half* W1s = (__half*)(gsm + 65536);       // [y=32][k=32][c=32]
    float*  ghs = (float*)(gsm + 131072);       // [r=32][q=32]
    int cchunk = blockIdx.x, b = blockIdx.y, t = threadIdx.x;
    int cc = cchunk*32;

    for (int idx = t; idx < 1024; idx += 256) {
        int r = idx >> 5, q = idx & 31;
        ghs[idx] = g_ghat[q*32 + r];
    }
    // load fT slice: 1024 rows x 32 channels (4 uint4 per row)
    for (int idx = t; idx < 4096; idx += 256) {
        int p = idx >> 2, q = idx & 3;
        ((uint4*)fTs)[idx] =
            *(const uint4*)(g_fT + ((size_t)(b*HW + p))*CH + cc + q*8);
    }
    __syncthreads();

    int c = t & 31, kq = t >> 5;   // kq = 0..7 -> 4 k (stage A) / 4 i (stage B)

    // stage A: W1[y][k][c] = sum_x ghat[k][x] * fT[y*32+x][c]
    for (int y = 0; y < 32; y++) {
        float a0 = 0.f, a1 = 0.f, a2 = 0.f, a3 = 0.f;
        const __half* fr = fTs + (y*32)*32 + c;
        #pragma unroll 8
        for (int x = 0; x < 32; x++) {
            float v = __half2float(fr[x*32]);
            float4 g4 = *(const float4*)&ghs[x*32 + kq*4];
            a0 += g4.x*v; a1 += g4.y*v; a2 += g4.z*v; a3 += g4.w*v;
        }
        __half* wr = W1s + (y*32 + kq*4)*32 + c;
        wr[0]  = __float2half_rn(a0);
        wr[32] = __float2half_rn(a1);
        wr[64] = __float2half_rn(a2);
        wr[96] = __float2half_rn(a3);
    }
    __syncthreads();

    // stage B: out[(i*32+k)][c] = sum_y ghat[i][y] * W1[y][k][c]
    // viewed layout: row = i*16 + (k>>1), col = (k&1)*512 + cc + c
    for (int k = 0; k < 32; k++) {
        float a0 = 0.f, a1 = 0.f, a2 = 0.f, a3 = 0.f;
        const __half* wr = W1s + k*32 + c;
        #pragma unroll 8
        for (int y = 0; y < 32; y++) {
            float v = __half2float(wr[y*1024]);
            float4 g4 = *(const float4*)&ghs[y*32 + kq*4];
            a0 += g4.x*v; a1 += g4.y*v; a2 += g4.z*v; a3 += g4.w*v;
        }
        int half = k & 1, kr = k >> 1;
        size_t colo = (size_t)(half*512 + cc + c);
        g_Bh[((size_t)(b*1024 + (kq*4+0)*16 + kr))*1024 + colo] = __float2half_rn(a0);
        g_Bh[((size_t)(b*1024 + (kq*4+1)*16 + kr))*1024 + colo] = __float2half_rn(a1);
        g_Bh[((size_t)(b*1024 + (kq*4+2)*16 + kr))*1024 + colo] = __float2half_rn(a2);
        g_Bh[((size_t)(b*1024 + (kq*4+3)*16 + kr))*1024 + colo] = __float2half_rn(a3);
    }
}

// ---------------- 3x3 patch self-attention, 4x4 pixel tiles (R9 form) ------
__global__ void __launch_bounds__(256) k_attn() {
    __shared__ uint32_t sig2[36*256];
    __shared__ float attw[16][9];
    int tx0 = blockIdx.x*4, ty0 = blockIdx.y*4, b = blockIdx.z;
    int t = threadIdx.x, lane = t & 31, w = t >> 5;
    const uint32_t* gsig = (const uint32_t*)g_sigT + (size_t)b*HW*256;

    for (int e = t; e < 9216; e += 256) {
        int r = e >> 8, c2 = e & 255;
        int j = r/6, i = r - j*6;
        int ny = ty0 - 1 + j, nx = tx0 - 1 + i;
        uint32_t v = 0;
        if (ny >= 0 && ny < 32 && nx >= 0 && nx < 32)
            v = gsig[(size_t)(ny*32 + nx)*256 + c2];
        sig2[e] = v;
    }
    __syncthreads();

    #pragma unroll
    for (int qq = 0; qq < 2; qq++) {
        int q = w*2 + qq, py = q >> 2, px = q & 3;
        int rc = (py+1)*6 + (px+1);
        float acc[9];
        #pragma unroll
        for (int k = 0; k < 9; k++) acc[k] = 0.f;
        #pragma unroll
        for (int i = 0; i < 4; i++) {
            int c2 = lane*2 + i*64;
            uint2 ce = *(const uint2*)&sig2[rc*256 + c2];
            float2 c0 = bf2f(ce.x), c1 = bf2f(ce.y);
            #pragma unroll
            for (int k = 0; k < 9; k++) {
                int rk = rc + (k/3 - 1)*6 + (k%3 - 1);
                uint2 ne = *(const uint2*)&sig2[rk*256 + c2];
                float2 n0 = bf2f(ne.x), n1 = bf2f(ne.y);
                acc[k] += c0.x*n0.x + c0.y*n0.y + c1.x*n1.x + c1.y*n1.y;
            }
        }
        #pragma unroll
        for (int k = 0; k < 9; k++)
            #pragma unroll
            for (int o = 16; o; o >>= 1) acc[k] += __shfl_xor_sync(~0u, acc[k], o);
        float lg[9], m = -1e30f;
        #pragma unroll
        for (int k = 0; k < 9; k++) { lg[k] = acc[k]*(1.0f/CH); m = fmaxf(m, lg[k]); }
        float den = 0.f, e9[9];
        #pragma unroll
        for (int k = 0; k < 9; k++) { e9[k] = __expf(lg[k]-m); den += e9[k]; }
        float rd = 1.f/den;
        if (lane == 0) {
            #pragma unroll
            for (int k = 0; k < 9; k++) attw[q][k] = e9[k]*rd;
        }
    }
    __syncthreads();

    int q = t >> 4, l16 = t & 15;
    int py = q >> 2, px = q & 3;
    int yy0 = ty0 + py, xx0 = tx0 + px;
    int p = yy0*32 + xx0;
    float aw[9]; int pn[9]; bool valid[9];
    #pragma unroll
    for (int k = 0; k < 9; k++) {
        int dy = k/3 - 1, dx = k%3 - 1;
        int ny = yy0 + dy, nx = xx0 + dx;
        valid[k] = (ny >= 0 && ny < 32 && nx >= 0 && nx < 32);
        pn[k] = ny*32 + nx;
        aw[k] = attw[q][k];
    }
    size_t fbase = (size_t)b*HW;
    size_t obase = ((size_t)(b*1024 + 512 + (p >> 1)))*1024 + (p & 1)*512;
    #pragma unroll
    for (int j = 0; j < 4; j++) {
        int c = l16*8 + j*128;
        float g0 = 0.f, g1 = 0.f, g2 = 0.f, g3 = 0.f, g4 = 0.f, g5 = 0.f, g6 = 0.f, g7 = 0.f;
        #pragma unroll
        for (int k = 0; k < 9; k++) {
            if (valid[k]) {
                uint4 u = *(const uint4*)&g_fT[(fbase + pn[k])*CH + c];
                float2 a0 = hf2f(u.x), a1 = hf2f(u.y), a2 = hf2f(u.z), a3 = hf2f(u.w);
                float wgt = aw[k];
                g0 += wgt*a0.x; g1 += wgt*a0.y; g2 += wgt*a1.x; g3 += wgt*a1.y;
                g4 += wgt*a2.x; g5 += wgt*a2.y; g6 += wgt*a3.x; g7 += wgt*a3.y;
            }
        }
        __half2 h0 = __floats2half2_rn(g0, g1), h1 = __floats2half2_rn(g2, g3);
        __half2 h2 = __floats2half2_rn(g4, g5), h3 = __floats2half2_rn(g6, g7);
        uint4 o;
        o.x = *(uint32_t*)&h0; o.y = *(uint32_t*)&h1;
        o.z = *(uint32_t*)&h2; o.w = *(uint32_t*)&h3;
        *(uint4*)&g_Bh[obase + c] = o;
    }
}

// ---------------- down GEMM via mma.sync fp16, 3-stage pipeline ------------
__global__ void __launch_bounds__(256, 2) k_down_mma() {
    __shared__ __half As[3][128*32];
    __shared__ __half Bs[3][32*128];
    int t = threadIdx.x, lane = t & 31, wid = t >> 5;
    int m0 = blockIdx.x*128, n0 = blockIdx.y*128, b = blockIdx.z;
    int wm = (wid & 3)*32, wn = (wid >> 2)*64;
    const __half* Bb = g_Bh + (size_t)b*1024*1024;

    float acc[2][8][4];
    #pragma unroll
    for (int i = 0; i < 2; i++)
        #pragma unroll
        for (int j = 0; j < 8; j++)
            #pragma unroll
            for (int r = 0; r < 4; r++) acc[i][j][r] = 0.f;

    auto load_stage = [&](int kb, int s) {
        int kp = kb*32;
        uint32_t sa = smem_u32(&As[s][0]);
        uint32_t sb2 = smem_u32(&Bs[s][0]);
        #pragma unroll
        for (int i = 0; i < 2; i++) {
            int ch = t + i*256;
            int row = ch >> 2, c4 = ch & 3;
            cpasync16(sa + swz(row*64 + c4*16),
                      g_A + ((size_t)(m0+row)*1024 + kp + c4*8));
            int br = ch >> 4, bc = ch & 15;
            cpasync16(sb2 + br*256 + ((bc ^ (br & 7)) << 4),
                      Bb + (size_t)(kp+br)*1024 + n0 + bc*8);
        }
        cp_commit();
    };

    load_stage(0, 0);
    load_stage(1, 1);

    for (int kb = 0; kb < 32; kb++) {
        int s = kb - (kb/3)*3;
        if (kb < 31) cp_wait1(); else cp_wait0();
        __syncthreads();
        if (kb + 2 < 32) load_stage(kb+2, (kb+2) - ((kb+2)/3)*3);

        uint32_t abase = smem_u32(&As[s][0]);
        uint32_t bbase = smem_u32(&Bs[s][0]);
        int tl = lane >> 3, rw = lane & 7;
        #pragma unroll
        for (int k16 = 0; k16 < 2; k16++) {
            int k0 = k16*16;
            uint32_t bfr[4][4];
            #pragma unroll
            for (int j2 = 0; j2 < 4; j2++) {
                int krow = k0 + (tl & 1)*8 + rw;
                int ncol = wn + j2*16 + (tl >> 1)*8;
                uint32_t bd = bbase + krow*256 + ((((ncol >> 3) ^ (krow & 7)) << 4));
                asm volatile("ldmatrix.sync.aligned.m8n8.x4.trans.shared.b16 {%0,%1,%2,%3}, [%4];"
                             : "=r"(bfr[j2][0]), "=r"(bfr[j2][1]), "=r"(bfr[j2][2]), "=r"(bfr[j2][3])
                             : "r"(bd));
            }
            uint32_t af[2][4];
            #pragma unroll
            for (int i = 0; i < 2; i++) {
                int mm = wm + i*16 + (tl & 1)*8 + rw;
                int kk = k0 + (tl >> 1)*8;
                uint32_t ad = abase + swz((uint32_t)(mm*64 + kk*2));
                asm volatile("ldmatrix.sync.aligned.m8n8.x4.shared.b16 {%0,%1,%2,%3}, [%4];"
                             : "=r"(af[i][0]), "=r"(af[i][1]), "=r"(af[i][2]), "=r"(af[i][3])
                             : "r"(ad));
            }
            #pragma unroll
            for (int i = 0; i < 2; i++)
                #pragma unroll
                for (int j = 0; j < 8; j++) {
                    uint32_t b0 = bfr[j >> 1][(j & 1)*2 + 0];
                    uint32_t b1 = bfr[j >> 1][(j & 1)*2 + 1];
                    asm volatile(
                        "mma.sync.aligned.m16n8k16.row.col.f32.f16.f16.f32 "
                        "{%0,%1,%2,%3}, {%4,%5,%6,%7}, {%8,%9}, {%0,%1,%2,%3};"
                        : "+f"(acc[i][j][0]), "+f"(acc[i][j][1]),
                          "+f"(acc[i][j][2]), "+f"(acc[i][j][3])
                        : "r"(af[i][0]), "r"(af[i][1]), "r"(af[i][2]), "r"(af[i][3]),
                          "r"(b0), "r"(b1));
                }
        }
    }

    float* Cm = g_z + (size_t)b*512*1024;
    #pragma unroll
    for (int i = 0; i < 2; i++) {
        int mrow = m0 + wm + i*16 + (lane >> 2);
        #pragma unroll
        for (int j = 0; j < 8; j++) {
            int n = n0 + wn + j*8 + (lane & 3)*2;
            *(float2*)&Cm[(size_t)mrow*1024 + n]     = make_float2(acc[i][j][0], acc[i][j][1]);
            *(float2*)&Cm[(size_t)(mrow+8)*1024 + n] = make_float2(acc[i][j][2], acc[i][j][3]);
        }
    }
}

// ---------------- fused InstanceNorm + LeakyReLU (float4) ------------------
__global__ void k_finish(float* __restrict__ out) {
    int o = blockIdx.x, b = blockIdx.y, t = threadIdx.x;
    size_t base = (size_t)(b*CH + o)*HW;
    float4 v = ((const float4*)(g_z + base))[t];
    float s = v.x + v.y + v.z + v.w;
    float sq = v.x*v.x + v.y*v.y + v.z*v.z + v.w*v.w;
    #pragma unroll
    for (int o2 = 16; o2; o2 >>= 1) {
        s  += __shfl_xor_sync(~0u, s,  o2);
        sq += __shfl_xor_sync(~0u, sq, o2);
    }
    __shared__ float ws[8][2];
    __shared__ float smu, srs;
    if ((t & 31) == 0) { ws[t>>5][0] = s; ws[t>>5][1] = sq; }
    __syncthreads();
    if (t == 0) {
        float S = 0.f, Q = 0.f;
        #pragma unroll
        for (int w = 0; w < 8; w++) { S += ws[w][0]; Q += ws[w][1]; }
        float mu = S*(1.0f/HW);
        float var = Q*(1.0f/HW) - mu*mu;
        smu = mu; srs = rsqrtf(var + 1e-5f);
    }
    __syncthreads();
    float4 r;
    r.x = (v.x - smu)*srs; r.x = r.x >= 0.f ? r.x : 0.2f*r.x;
    r.y = (v.y - smu)*srs; r.y = r.y >= 0.f ? r.y : 0.2f*r.y;
    r.z = (v.z - smu)*srs; r.z = r.z >= 0.f ? r.z : 0.2f*r.z;
    r.w = (v.w - smu)*srs; r.w = r.w >= 0.f ? r.w : 0.2f*r.w;
    ((float4*)(out + base))[t] = r;
}

// ---------------- launch (serial) -------------------------------------------
extern "C" void kernel_launch(void* const* d_in, const int* in_sizes, int n_in,
                              void* d_out, int out_size) {
    const float* x   = (const float*)d_in[0];
    const float* w1  = (const float*)d_in[1];
    const float* b1  = (const float*)d_in[2];
    const float* w2  = (const float*)d_in[3];
    const float* b2  = (const float*)d_in[4];
    const float* dw  = (const float*)d_in[5];
    const float* gus = (const float*)d_in[6];
    float* out = (float*)d_out;

    static int init = 0;
    if (!init) {
        cudaFuncSetAttribute(k_gus, cudaFuncAttributeMaxDynamicSharedMemorySize, GUS_SMEM);
        init = 1;
    }

    k_pre<<<513, 1024>>>(dw, gus);
    k_se_reduce<<<dim3(CH, NB), 128>>>(x);
    k_se_mlp<<<NB, 512>>>(w1, b1, w2, b2);
    k_makeT<<<dim3(32, 16, NB), dim3(32, 8)>>>(x);
    k_gus<<<dim3(16, NB), 256, GUS_SMEM>>>();
    k_attn<<<dim3(8, 8, NB), 256>>>();
    k_down_mma<<<dim3(4, 8, NB), 256>>>();
    k_finish<<<dim3(CH, NB), 256>>>(out);
}

// round 15
// speedup vs baseline: 1.0544x; 1.0544x over previous
#include <cuda_runtime.h>
#include <cuda_bf16.h>
#include <cuda_fp16.h>
#include <math.h>
#include <stdint.h>

#define NB 16
#define CH 512
#define HW 1024

// ---------------- scratch (static device globals) --------------------------
__device__ float g_ghat[32*32];
__device__ float g_s[NB*CH];
__device__ float g_ysc[NB*CH];
__device__ __half g_fT[(size_t)NB*HW*CH];
__device__ __nv_bfloat16 g_sigT[(size_t)NB*HW*CH];
__device__ __half g_w1buf[(size_t)NB*32*32*CH];
__device__ float g_z[(size_t)NB*CH*HW];
__device__ __half g_A[(size_t)512*1024];
__device__ __half g_Bh[(size_t)NB*1024*1024];

// ---------------- PTX helpers ----------------------------------------------
__device__ __forceinline__ uint32_t smem_u32(const void* p) {
    uint32_t a;
    asm("{ .reg .u64 t; cvta.to.shared.u64 t, %1; cvt.u32.u64 %0, t; }" : "=r"(a) : "l"(p));
    return a;
}
__device__ __forceinline__ void cpasync16(uint32_t saddr, const void* gaddr) {
    asm volatile("cp.async.cg.shared.global [%0], [%1], 16;" :: "r"(saddr), "l"(gaddr) : "memory");
}
__device__ __forceinline__ void cp_commit() { asm volatile("cp.async.commit_group;" ::: "memory"); }
__device__ __forceinline__ void cp_wait1() { asm volatile("cp.async.wait_group 1;" ::: "memory"); }
__device__ __forceinline__ void cp_wait0() { asm volatile("cp.async.wait_group 0;" ::: "memory"); }
__device__ __forceinline__ uint32_t swz(uint32_t x) { return x ^ ((x >> 3) & 0x70); }
__device__ __forceinline__ float2 bf2f(uint32_t u) {
    __nv_bfloat162 h = *reinterpret_cast<__nv_bfloat162*>(&u);
    return __bfloat1622float2(h);
}
__device__ __forceinline__ float2 hf2f(uint32_t u) {
    __half2 h = *reinterpret_cast<__half2*>(&u);
    return __half22float2(h);
}

// ---------------- convA + ghat (merged, one launch) -------------------------
__global__ void k_pre(const float* __restrict__ Wd, const float* __restrict__ gus) {
    if (blockIdx.x < 512) {
        int r = blockIdx.x, c = threadIdx.x;
        g_A[(size_t)r*1024 + c] = __float2half_rn(Wd[(size_t)r*1024 + c]);
    } else {
        int t = threadIdx.x;
        int i = t >> 5, y = t & 31;
        const float* p = gus + (size_t)(i*32)*1024 + y*32;
        float s = 0.f;
        #pragma unroll
        for (int x = 0; x < 32; x++) s += p[x];
        g_ghat[t] = s;
    }
}

// ---------------- SE: spatial mean (float4) --------------------------------
__global__ void k_se_reduce(const float* __restrict__ x) {
    int c = blockIdx.x, b = blockIdx.y, t = threadIdx.x;
    const float4* p = (const float4*)(x + ((size_t)(b*CH + c))*HW);
    float s = 0.f;
    #pragma unroll
    for (int j = 0; j < 2; j++) {
        float4 v = p[t + j*128];
        s += v.x + v.y + v.z + v.w;
    }
    #pragma unroll
    for (int o = 16; o; o >>= 1) s += __shfl_xor_sync(~0u, s, o);
    __shared__ float ws[4];
    if ((t & 31) == 0) ws[t >> 5] = s;
    __syncthreads();
    if (t == 0) g_s[b*CH + c] = (ws[0]+ws[1]+ws[2]+ws[3]) * (1.0f/HW);
}

// ---------------- SE: tiny MLP ---------------------------------------------
__global__ void k_se_mlp(const float* __restrict__ w1, const float* __restrict__ b1,
                         const float* __restrict__ w2, const float* __restrict__ b2) {
    int b = blockIdx.x, t = threadIdx.x;
    __shared__ float ssh[CH];
    __shared__ float hsh[32];
    ssh[t] = g_s[b*CH + t];
    __syncthreads();
    if (t < 32) {
        float a = b1[t];
        const float* w = w1 + t*CH;
        for (int c = 0; c < CH; c++) a += w[c]*ssh[c];
        hsh[t] = fmaxf(a, 0.f);
    }
    __syncthreads();
    float a = b2[t];
    const float* w = w2 + t*32;
    #pragma unroll
    for (int j = 0; j < 32; j++) a += w[j]*hsh[j];
    g_ysc[b*CH + t] = 1.f/(1.f + __expf(-a));
}

// ---------------- out32 transpose + sigmoid (fT fp16, sigT bf16) -----------
__global__ void k_makeT(const float* __restrict__ x) {
    int p0 = blockIdx.x*32, c0 = blockIdx.y*32, b = blockIdx.z;
    int tx = threadIdx.x, ty = threadIdx.y;
    __shared__ float tile[32][33];
    #pragma unroll
    for (int i = 0; i < 4; i++) {
        int c = c0 + ty + i*8;
        tile[ty+i*8][tx] = x[((size_t)(b*CH + c))*HW + p0 + tx] * g_ysc[b*CH + c];
    }
    __syncthreads();
    #pragma unroll
    for (int i = 0; i < 4; i++) {
        int p = p0 + ty + i*8;
        float v = tile[tx][ty+i*8];
        size_t idx = ((size_t)(b*HW + p))*CH + c0 + tx;
        g_fT[idx] = __float2half_rn(v);
        g_sigT[idx] = __float2bfloat16(1.f/(1.f + __expf(-v)));
    }
}

// ---------------- gus stage A (fp16 in/out, fp32 accum) --------------------
__global__ void k_gusA() {
    int y = blockIdx.x, b = blockIdx.y, t = threadIdx.x;
    __shared__ float ghT[1024];
    __shared__ float slab[32][256];
    for (int idx = t; idx < 1024; idx += 256) {
        int xx = idx >> 5, k = idx & 31;
        ghT[idx] = g_ghat[k*32 + xx];
    }
    for (int cc = 0; cc < CH; cc += 256) {
        __syncthreads();
        for (int idx = t; idx < 32*128; idx += 256) {
            int xr = idx >> 7, c2 = idx & 127;
            uint32_t u = ((const uint32_t*)(g_fT + ((size_t)(b*HW + y*32 + xr))*CH + cc))[c2];
            float2 f = hf2f(u);
            slab[xr][c2*2] = f.x; slab[xr][c2*2+1] = f.y;
        }
        __syncthreads();
        float acc[32];
        #pragma unroll
        for (int k = 0; k < 32; k++) acc[k] = 0.f;
        #pragma unroll
        for (int xx = 0; xx < 32; xx++) {
            float v = slab[xx][t];
            const float4* gp = (const float4*)&ghT[xx*32];
            #pragma unroll
            for (int q = 0; q < 8; q++) {
                float4 g4 = gp[q];
                acc[q*4+0] += g4.x*v; acc[q*4+1] += g4.y*v;
                acc[q*4+2] += g4.z*v; acc[q*4+3] += g4.w*v;
            }
        }
        #pragma unroll
        for (int k = 0; k < 32; k++)
            g_w1buf[((size_t)((b*32 + y)*32 + k))*CH + cc + t] = __float2half_rn(acc[k]);
    }
}

// ---------------- gus stage B (fp16 in) -> fp16 act ------------------------
__global__ void k_gusB() {
    int k = blockIdx.x, b = blockIdx.y, t = threadIdx.x;
    __shared__ float ghB[1024];
    __shared__ float slab[32][256];
    for (int idx = t; idx < 1024; idx += 256) {
        int yy = idx >> 5, i = idx & 31;
        ghB[idx] = g_ghat[i*32 + yy];
    }
    int half = k & 1, kr = k >> 1;
    for (int cc = 0; cc < CH; cc += 256) {
        __syncthreads();
        for (int idx = t; idx < 32*128; idx += 256) {
            int yr = idx >> 7, c2 = idx & 127;
            uint32_t u = ((const uint32_t*)(g_w1buf + ((size_t)((b*32 + yr)*32 + k))*CH + cc))[c2];
            float2 f = hf2f(u);
            slab[yr][c2*2] = f.x; slab[yr][c2*2+1] = f.y;
        }
        __syncthreads();
        float acc[32];
        #pragma unroll
        for (int i = 0; i < 32; i++) acc[i] = 0.f;
        #pragma unroll
        for (int yy = 0; yy < 32; yy++) {
            float v = slab[yy][t];
            const float4* gp = (const float4*)&ghB[yy*32];
            #pragma unroll
            for (int q = 0; q < 8; q++) {
                float4 g4 = gp[q];
                acc[q*4+0] += g4.x*v; acc[q*4+1] += g4.y*v;
                acc[q*4+2] += g4.z*v; acc[q*4+3] += g4.w*v;
            }
        }
        #pragma unroll
        for (int i = 0; i < 32; i++)
            g_Bh[((size_t)(b*1024 + i*16 + kr))*1024 + half*512 + cc + t] =
                __float2half_rn(acc[i]);
    }
}

// ---------------- 3x3 patch self-attention, 4x4 pixel tiles ----------------
__global__ void __launch_bounds__(256) k_attn() {
    __shared__ uint32_t sig2[36*256];
    __shared__ float attw[16][9];
    int tx0 = blockIdx.x*4, ty0 = blockIdx.y*4, b = blockIdx.z;
    int t = threadIdx.x, lane = t & 31, w = t >> 5;
    const uint32_t* gsig = (const uint32_t*)g_sigT + (size_t)b*HW*256;

    for (int e = t; e < 9216; e += 256) {
        int r = e >> 8, c2 = e & 255;
        int j = r/6, i = r - j*6;
        int ny = ty0 - 1 + j, nx = tx0 - 1 + i;
        uint32_t v = 0;
        if (ny >= 0 && ny < 32 && nx >= 0 && nx < 32)
            v = gsig[(size_t)(ny*32 + nx)*256 + c2];
        sig2[e] = v;
    }
    __syncthreads();

    #pragma unroll
    for (int qq = 0; qq < 2; qq++) {
        int q = w*2 + qq, py = q >> 2, px = q & 3;
        int rc = (py+1)*6 + (px+1);
        float acc[9];
        #pragma unroll
        for (int k = 0; k < 9; k++) acc[k] = 0.f;
        #pragma unroll
        for (int i = 0; i < 4; i++) {
            int c2 = lane*2 + i*64;
            uint2 ce = *(const uint2*)&sig2[rc*256 + c2];
            float2 c0 = bf2f(ce.x), c1 = bf2f(ce.y);
            #pragma unroll
            for (int k = 0; k < 9; k++) {
                int rk = rc + (k/3 - 1)*6 + (k%3 - 1);
                uint2 ne = *(const uint2*)&sig2[rk*256 + c2];
                float2 n0 = bf2f(ne.x), n1 = bf2f(ne.y);
                acc[k] += c0.x*n0.x + c0.y*n0.y + c1.x*n1.x + c1.y*n1.y;
            }
        }
        #pragma unroll
        for (int k = 0; k < 9; k++)
            #pragma unroll
            for (int o = 16; o; o >>= 1) acc[k] += __shfl_xor_sync(~0u, acc[k], o);
        float lg[9], m = -1e30f;
        #pragma unroll
        for (int k = 0; k < 9; k++) { lg[k] = acc[k]*(1.0f/CH); m = fmaxf(m, lg[k]); }
        float den = 0.f, e9[9];
        #pragma unroll
        for (int k = 0; k < 9; k++) { e9[k] = __expf(lg[k]-m); den += e9[k]; }
        float rd = 1.f/den;
        if (lane == 0) {
            #pragma unroll
            for (int k = 0; k < 9; k++) attw[q][k] = e9[k]*rd;
        }
    }
    __syncthreads();

    int q = t >> 4, l16 = t & 15;
    int py = q >> 2, px = q & 3;
    int yy0 = ty0 + py, xx0 = tx0 + px;
    int p = yy0*32 + xx0;
    float aw[9]; int pn[9]; bool valid[9];
    #pragma unroll
    for (int k = 0; k < 9; k++) {
        int dy = k/3 - 1, dx = k%3 - 1;
        int ny = yy0 + dy, nx = xx0 + dx;
        valid[k] = (ny >= 0 && ny < 32 && nx >= 0 && nx < 32);
        pn[k] = ny*32 + nx;
        aw[k] = attw[q][k];
    }
    size_t fbase = (size_t)b*HW;
    size_t obase = ((size_t)(b*1024 + 512 + (p >> 1)))*1024 + (p & 1)*512;
    #pragma unroll
    for (int j = 0; j < 4; j++) {
        int c = l16*8 + j*128;
        float g0 = 0.f, g1 = 0.f, g2 = 0.f, g3 = 0.f, g4 = 0.f, g5 = 0.f, g6 = 0.f, g7 = 0.f;
        #pragma unroll
        for (int k = 0; k < 9; k++) {
            if (valid[k]) {
                uint4 u = *(const uint4*)&g_fT[(fbase + pn[k])*CH + c];
                float2 a0 = hf2f(u.x), a1 = hf2f(u.y), a2 = hf2f(u.z), a3 = hf2f(u.w);
                float wgt = aw[k];
                g0 += wgt*a0.x; g1 += wgt*a0.y; g2 += wgt*a1.x; g3 += wgt*a1.y;
                g4 += wgt*a2.x; g5 += wgt*a2.y; g6 += wgt*a3.x; g7 += wgt*a3.y;
            }
        }
        __half2 h0 = __floats2half2_rn(g0, g1), h1 = __floats2half2_rn(g2, g3);
        __half2 h2 = __floats2half2_rn(g4, g5), h3 = __floats2half2_rn(g6, g7);
        uint4 o;
        o.x = *(uint32_t*)&h0; o.y = *(uint32_t*)&h1;
        o.z = *(uint32_t*)&h2; o.w = *(uint32_t*)&h3;
        *(uint4*)&g_Bh[obase + c] = o;
    }
}

// ---------------- down GEMM via mma.sync fp16, 3-stage pipeline ------------
__global__ void __launch_bounds__(256, 2) k_down_mma() {
    __shared__ __half As[3][128*32];
    __shared__ __half Bs[3][32*128];
    int t = threadIdx.x, lane = t & 31, wid = t >> 5;
    int m0 = blockIdx.x*128, n0 = blockIdx.y*128, b = blockIdx.z;
    int wm = (wid & 3)*32, wn = (wid >> 2)*64;
    const __half* Bb = g_Bh + (size_t)b*1024*1024;

    float acc[2][8][4];
    #pragma unroll
    for (int i = 0; i < 2; i++)
        #pragma unroll
        for (int j = 0; j < 8; j++)
            #pragma unroll
            for (int r = 0; r < 4; r++) acc[i][j][r] = 0.f;

    auto load_stage = [&](int kb, int s) {
        int kp = kb*32;
        uint32_t sa = smem_u32(&As[s][0]);
        uint32_t sb2 = smem_u32(&Bs[s][0]);
        #pragma unroll
        for (int i = 0; i < 2; i++) {
            int ch = t + i*256;
            int row = ch >> 2, c4 = ch & 3;
            cpasync16(sa + swz(row*64 + c4*16),
                      g_A + ((size_t)(m0+row)*1024 + kp + c4*8));
            int br = ch >> 4, bc = ch & 15;
            cpasync16(sb2 + br*256 + ((bc ^ (br & 7)) << 4),
                      Bb + (size_t)(kp+br)*1024 + n0 + bc*8);
        }
        cp_commit();
    };

    load_stage(0, 0);
    load_stage(1, 1);

    for (int kb = 0; kb < 32; kb++) {
        int s = kb - (kb/3)*3;
        if (kb < 31) cp_wait1(); else cp_wait0();
        __syncthreads();
        if (kb + 2 < 32) load_stage(kb+2, (kb+2) - ((kb+2)/3)*3);

        uint32_t abase = smem_u32(&As[s][0]);
        uint32_t bbase = smem_u32(&Bs[s][0]);
        int tl = lane >> 3, rw = lane & 7;
        #pragma unroll
        for (int k16 = 0; k16 < 2; k16++) {
            int k0 = k16*16;
            uint32_t bfr[4][4];
            #pragma unroll
            for (int j2 = 0; j2 < 4; j2++) {
                int krow = k0 + (tl & 1)*8 + rw;
                int ncol = wn + j2*16 + (tl >> 1)*8;
                uint32_t bd = bbase + krow*256 + ((((ncol >> 3) ^ (krow & 7)) << 4));
                asm volatile("ldmatrix.sync.aligned.m8n8.x4.trans.shared.b16 {%0,%1,%2,%3}, [%4];"
                             : "=r"(bfr[j2][0]), "=r"(bfr[j2][1]), "=r"(bfr[j2][2]), "=r"(bfr[j2][3])
                             : "r"(bd));
            }
            uint32_t af[2][4];
            #pragma unroll
            for (int i = 0; i < 2; i++) {
                int mm = wm + i*16 + (tl & 1)*8 + rw;
                int kk = k0 + (tl >> 1)*8;
                uint32_t ad = abase + swz((uint32_t)(mm*64 + kk*2));
                asm volatile("ldmatrix.sync.aligned.m8n8.x4.shared.b16 {%0,%1,%2,%3}, [%4];"
                             : "=r"(af[i][0]), "=r"(af[i][1]), "=r"(af[i][2]), "=r"(af[i][3])
                             : "r"(ad));
            }
            #pragma unroll
            for (int i = 0; i < 2; i++)
                #pragma unroll
                for (int j = 0; j < 8; j++) {
                    uint32_t b0 = bfr[j >> 1][(j & 1)*2 + 0];
                    uint32_t b1 = bfr[j >> 1][(j & 1)*2 + 1];
                    asm volatile(
                        "mma.sync.aligned.m16n8k16.row.col.f32.f16.f16.f32 "
                        "{%0,%1,%2,%3}, {%4,%5,%6,%7}, {%8,%9}, {%0,%1,%2,%3};"
                        : "+f"(acc[i][j][0]), "+f"(acc[i][j][1]),
                          "+f"(acc[i][j][2]), "+f"(acc[i][j][3])
                        : "r"(af[i][0]), "r"(af[i][1]), "r"(af[i][2]), "r"(af[i][3]),
                          "r"(b0), "r"(b1));
                }
        }
    }

    float* Cm = g_z + (size_t)b*512*1024;
    #pragma unroll
    for (int i = 0; i < 2; i++) {
        int mrow = m0 + wm + i*16 + (lane >> 2);
        #pragma unroll
        for (int j = 0; j < 8; j++) {
            int n = n0 + wn + j*8 + (lane & 3)*2;
            *(float2*)&Cm[(size_t)mrow*1024 + n]     = make_float2(acc[i][j][0], acc[i][j][1]);
            *(float2*)&Cm[(size_t)(mrow+8)*1024 + n] = make_float2(acc[i][j][2], acc[i][j][3]);
        }
    }
}

// ---------------- fused InstanceNorm + LeakyReLU (float4) ------------------
__global__ void k_finish(float* __restrict__ out) {
    int o = blockIdx.x, b = blockIdx.y, t = threadIdx.x;
    size_t base = (size_t)(b*CH + o)*HW;
    float4 v = ((const float4*)(g_z + base))[t];
    float s = v.x + v.y + v.z + v.w;
    float sq = v.x*v.x + v.y*v.y + v.z*v.z + v.w*v.w;
    #pragma unroll
    for (int o2 = 16; o2; o2 >>= 1) {
        s  += __shfl_xor_sync(~0u, s,  o2);
        sq += __shfl_xor_sync(~0u, sq, o2);
    }
    __shared__ float ws[8][2];
    __shared__ float smu, srs;
    if ((t & 31) == 0) { ws[t>>5][0] = s; ws[t>>5][1] = sq; }
    __syncthreads();
    if (t == 0) {
        float S = 0.f, Q = 0.f;
        #pragma unroll
        for (int w = 0; w < 8; w++) { S += ws[w][0]; Q += ws[w][1]; }
        float mu = S*(1.0f/HW);
        float var = Q*(1.0f/HW) - mu*mu;
        smu = mu; srs = rsqrtf(var + 1e-5f);
    }
    __syncthreads();
    float4 r;
    r.x = (v.x - smu)*srs; r.x = r.x >= 0.f ? r.x : 0.2f*r.x;
    r.y = (v.y - smu)*srs; r.y = r.y >= 0.f ? r.y : 0.2f*r.y;
    r.z = (v.z - smu)*srs; r.z = r.z >= 0.f ? r.z : 0.2f*r.z;
    r.w = (v.w - smu)*srs; r.w = r.w >= 0.f ? r.w : 0.2f*r.w;
    ((float4*)(out + base))[t] = r;
}

// ---------------- launch (serial, R9 order, merged pre) ---------------------
extern "C" void kernel_launch(void* const* d_in, const int* in_sizes, int n_in,
                              void* d_out, int out_size) {
    const float* x   = (const float*)d_in[0];
    const float* w1  = (const float*)d_in[1];
    const float* b1  = (const float*)d_in[2];
    const float* w2  = (const float*)d_in[3];
    const float* b2  = (const float*)d_in[4];
    const float* dw  = (const float*)d_in[5];
    const float* gus = (const float*)d_in[6];
    float* out = (float*)d_out;

    k_pre<<<513, 1024>>>(dw, gus);
    k_se_reduce<<<dim3(CH, NB), 128>>>(x);
    k_se_mlp<<<NB, 512>>>(w1, b1, w2, b2);
    k_makeT<<<dim3(32, 16, NB), dim3(32, 8)>>>(x);
    k_gusA<<<dim3(32, NB), 256>>>();
    k_gusB<<<dim3(32, NB), 256>>>();
    k_attn<<<dim3(8, 8, NB), 256>>>();
    k_down_mma<<<dim3(4, 8, NB), 256>>>();
    k_finish<<<dim3(CH, NB), 256>>>(out);
}

// round 16
// speedup vs baseline: 1.0623x; 1.0076x over previous
#include <cuda_runtime.h>
#include <cuda_bf16.h>
#include <cuda_fp16.h>
#include <math.h>
#include <stdint.h>

#define NB 16
#define CH 512
#define HW 1024

// ---------------- scratch (static device globals) --------------------------
__device__ float g_ghat[32*32];
__device__ float g_s[NB*CH];
__device__ float g_ysc[NB*CH];
__device__ __half g_fT[(size_t)NB*HW*CH];
__device__ __nv_bfloat16 g_sigT[(size_t)NB*HW*CH];
__device__ __half g_w1buf[(size_t)NB*32*32*CH];
__device__ float g_z[(size_t)NB*CH*HW];
__device__ __half g_A[(size_t)512*1024];
__device__ __half g_Bh[(size_t)NB*1024*1024];

// ---------------- PTX helpers ----------------------------------------------
__device__ __forceinline__ uint32_t smem_u32(const void* p) {
    uint32_t a;
    asm("{ .reg .u64 t; cvta.to.shared.u64 t, %1; cvt.u32.u64 %0, t; }" : "=r"(a) : "l"(p));
    return a;
}
__device__ __forceinline__ void cpasync16(uint32_t saddr, const void* gaddr) {
    asm volatile("cp.async.cg.shared.global [%0], [%1], 16;" :: "r"(saddr), "l"(gaddr) : "memory");
}
__device__ __forceinline__ void cp_commit() { asm volatile("cp.async.commit_group;" ::: "memory"); }
__device__ __forceinline__ void cp_wait1() { asm volatile("cp.async.wait_group 1;" ::: "memory"); }
__device__ __forceinline__ void cp_wait0() { asm volatile("cp.async.wait_group 0;" ::: "memory"); }
__device__ __forceinline__ uint32_t swz(uint32_t x) { return x ^ ((x >> 3) & 0x70); }
__device__ __forceinline__ float2 bf2f(uint32_t u) {
    __nv_bfloat162 h = *reinterpret_cast<__nv_bfloat162*>(&u);
    return __bfloat1622float2(h);
}
__device__ __forceinline__ float2 hf2f(uint32_t u) {
    __half2 h = *reinterpret_cast<__half2*>(&u);
    return __half22float2(h);
}

// ---------------- convA + ghat (merged, one launch) -------------------------
__global__ void k_pre(const float* __restrict__ Wd, const float* __restrict__ gus) {
    if (blockIdx.x < 512) {
        int r = blockIdx.x, c = threadIdx.x;
        g_A[(size_t)r*1024 + c] = __float2half_rn(Wd[(size_t)r*1024 + c]);
    } else {
        int t = threadIdx.x;
        int i = t >> 5, y = t & 31;
        const float* p = gus + (size_t)(i*32)*1024 + y*32;
        float s = 0.f;
        #pragma unroll
        for (int x = 0; x < 32; x++) s += p[x];
        g_ghat[t] = s;
    }
}

// ---------------- SE: spatial mean (float4, 2 channels per block) ----------
__global__ void k_se_reduce(const float* __restrict__ x) {
    int t = threadIdx.x;                    // 256 threads = 2 groups of 128
    int grp = t >> 7, th = t & 127;
    int c = blockIdx.x*2 + grp, b = blockIdx.y;
    const float4* p = (const float4*)(x + ((size_t)(b*CH + c))*HW);
    float s = 0.f;
    #pragma unroll
    for (int j = 0; j < 2; j++) {
        float4 v = p[th + j*128];
        s += v.x + v.y + v.z + v.w;
    }
    #pragma unroll
    for (int o = 16; o; o >>= 1) s += __shfl_xor_sync(~0u, s, o);
    __shared__ float ws[2][4];
    if ((th & 31) == 0) ws[grp][th >> 5] = s;
    __syncthreads();
    if (th == 0)
        g_s[b*CH + c] = (ws[grp][0]+ws[grp][1]+ws[grp][2]+ws[grp][3]) * (1.0f/HW);
}

// ---------------- SE: tiny MLP ---------------------------------------------
__global__ void k_se_mlp(const float* __restrict__ w1, const float* __restrict__ b1,
                         const float* __restrict__ w2, const float* __restrict__ b2) {
    int b = blockIdx.x, t = threadIdx.x;
    __shared__ float ssh[CH];
    __shared__ float hsh[32];
    ssh[t] = g_s[b*CH + t];
    __syncthreads();
    if (t < 32) {
        float a = b1[t];
        const float* w = w1 + t*CH;
        for (int c = 0; c < CH; c++) a += w[c]*ssh[c];
        hsh[t] = fmaxf(a, 0.f);
    }
    __syncthreads();
    float a = b2[t];
    const float* w = w2 + t*32;
    #pragma unroll
    for (int j = 0; j < 32; j++) a += w[j]*hsh[j];
    g_ysc[b*CH + t] = 1.f/(1.f + __expf(-a));
}

// ---------------- out32 transpose + sigmoid (fT fp16, sigT bf16) -----------
__global__ void k_makeT(const float* __restrict__ x) {
    int p0 = blockIdx.x*32, c0 = blockIdx.y*32, b = blockIdx.z;
    int tx = threadIdx.x, ty = threadIdx.y;
    __shared__ float tile[32][33];
    #pragma unroll
    for (int i = 0; i < 4; i++) {
        int c = c0 + ty + i*8;
        tile[ty+i*8][tx] = x[((size_t)(b*CH + c))*HW + p0 + tx] * g_ysc[b*CH + c];
    }
    __syncthreads();
    #pragma unroll
    for (int i = 0; i < 4; i++) {
        int p = p0 + ty + i*8;
        float v = tile[tx][ty+i*8];
        size_t idx = ((size_t)(b*HW + p))*CH + c0 + tx;
        g_fT[idx] = __float2half_rn(v);
        g_sigT[idx] = __float2bfloat16(1.f/(1.f + __expf(-v)));
    }
}

// ---------------- gus stage A (fp16 in/out, fp32 accum) --------------------
__global__ void k_gusA() {
    int y = blockIdx.x, b = blockIdx.y, t = threadIdx.x;
    __shared__ float ghT[1024];
    __shared__ float slab[32][256];
    for (int idx = t; idx < 1024; idx += 256) {
        int xx = idx >> 5, k = idx & 31;
        ghT[idx] = g_ghat[k*32 + xx];
    }
    for (int cc = 0; cc < CH; cc += 256) {
        __syncthreads();
        for (int idx = t; idx < 32*128; idx += 256) {
            int xr = idx >> 7, c2 = idx & 127;
            uint32_t u = ((const uint32_t*)(g_fT + ((size_t)(b*HW + y*32 + xr))*CH + cc))[c2];
            float2 f = hf2f(u);
            slab[xr][c2*2] = f.x; slab[xr][c2*2+1] = f.y;
        }
        __syncthreads();
        float acc[32];
        #pragma unroll
        for (int k = 0; k < 32; k++) acc[k] = 0.f;
        #pragma unroll
        for (int xx = 0; xx < 32; xx++) {
            float v = slab[xx][t];
            const float4* gp = (const float4*)&ghT[xx*32];
            #pragma unroll
            for (int q = 0; q < 8; q++) {
                float4 g4 = gp[q];
                acc[q*4+0] += g4.x*v; acc[q*4+1] += g4.y*v;
                acc[q*4+2] += g4.z*v; acc[q*4+3] += g4.w*v;
            }
        }
        #pragma unroll
        for (int k = 0; k < 32; k++)
            g_w1buf[((size_t)((b*32 + y)*32 + k))*CH + cc + t] = __float2half_rn(acc[k]);
    }
}

// ---------------- gus stage B (fp16 in) -> fp16 act ------------------------
__global__ void k_gusB() {
    int k = blockIdx.x, b = blockIdx.y, t = threadIdx.x;
    __shared__ float ghB[1024];
    __shared__ float slab[32][256];
    for (int idx = t; idx < 1024; idx += 256) {
        int yy = idx >> 5, i = idx & 31;
        ghB[idx] = g_ghat[i*32 + yy];
    }
    int half = k & 1, kr = k >> 1;
    for (int cc = 0; cc < CH; cc += 256) {
        __syncthreads();
        for (int idx = t; idx < 32*128; idx += 256) {
            int yr = idx >> 7, c2 = idx & 127;
            uint32_t u = ((const uint32_t*)(g_w1buf + ((size_t)((b*32 + yr)*32 + k))*CH + cc))[c2];
            float2 f = hf2f(u);
            slab[yr][c2*2] = f.x; slab[yr][c2*2+1] = f.y;
        }
        __syncthreads();
        float acc[32];
        #pragma unroll
        for (int i = 0; i < 32; i++) acc[i] = 0.f;
        #pragma unroll
        for (int yy = 0; yy < 32; yy++) {
            float v = slab[yy][t];
            const float4* gp = (const float4*)&ghB[yy*32];
            #pragma unroll
            for (int q = 0; q < 8; q++) {
                float4 g4 = gp[q];
                acc[q*4+0] += g4.x*v; acc[q*4+1] += g4.y*v;
                acc[q*4+2] += g4.z*v; acc[q*4+3] += g4.w*v;
            }
        }
        #pragma unroll
        for (int i = 0; i < 32; i++)
            g_Bh[((size_t)(b*1024 + i*16 + kr))*1024 + half*512 + cc + t] =
                __float2half_rn(acc[i]);
    }
}

// ---------------- 3x3 patch self-attention, 4x4 pixel tiles ----------------
__global__ void __launch_bounds__(256) k_attn() {
    __shared__ uint32_t sig2[36*256];
    __shared__ float attw[16][9];
    int tx0 = blockIdx.x*4, ty0 = blockIdx.y*4, b = blockIdx.z;
    int t = threadIdx.x, lane = t & 31, w = t >> 5;
    const uint32_t* gsig = (const uint32_t*)g_sigT + (size_t)b*HW*256;

    for (int e = t; e < 9216; e += 256) {
        int r = e >> 8, c2 = e & 255;
        int j = r/6, i = r - j*6;
        int ny = ty0 - 1 + j, nx = tx0 - 1 + i;
        uint32_t v = 0;
        if (ny >= 0 && ny < 32 && nx >= 0 && nx < 32)
            v = gsig[(size_t)(ny*32 + nx)*256 + c2];
        sig2[e] = v;
    }
    __syncthreads();

    #pragma unroll
    for (int qq = 0; qq < 2; qq++) {
        int q = w*2 + qq, py = q >> 2, px = q & 3;
        int rc = (py+1)*6 + (px+1);
        float acc[9];
        #pragma unroll
        for (int k = 0; k < 9; k++) acc[k] = 0.f;
        #pragma unroll
        for (int i = 0; i < 4; i++) {
            int c2 = lane*2 + i*64;
            uint2 ce = *(const uint2*)&sig2[rc*256 + c2];
            float2 c0 = bf2f(ce.x), c1 = bf2f(ce.y);
            #pragma unroll
            for (int k = 0; k < 9; k++) {
                int rk = rc + (k/3 - 1)*6 + (k%3 - 1);
                uint2 ne = *(const uint2*)&sig2[rk*256 + c2];
                float2 n0 = bf2f(ne.x), n1 = bf2f(ne.y);
                acc[k] += c0.x*n0.x + c0.y*n0.y + c1.x*n1.x + c1.y*n1.y;
            }
        }
        #pragma unroll
        for (int k = 0; k < 9; k++)
            #pragma unroll
            for (int o = 16; o; o >>= 1) acc[k] += __shfl_xor_sync(~0u, acc[k], o);
        float lg[9], m = -1e30f;
        #pragma unroll
        for (int k = 0; k < 9; k++) { lg[k] = acc[k]*(1.0f/CH); m = fmaxf(m, lg[k]); }
        float den = 0.f, e9[9];
        #pragma unroll
        for (int k = 0; k < 9; k++) { e9[k] = __expf(lg[k]-m); den += e9[k]; }
        float rd = 1.f/den;
        if (lane == 0) {
            #pragma unroll
            for (int k = 0; k < 9; k++) attw[q][k] = e9[k]*rd;
        }
    }
    __syncthreads();

    int q = t >> 4, l16 = t & 15;
    int py = q >> 2, px = q & 3;
    int yy0 = ty0 + py, xx0 = tx0 + px;
    int p = yy0*32 + xx0;
    float aw[9]; int pn[9]; bool valid[9];
    #pragma unroll
    for (int k = 0; k < 9; k++) {
        int dy = k/3 - 1, dx = k%3 - 1;
        int ny = yy0 + dy, nx = xx0 + dx;
        valid[k] = (ny >= 0 && ny < 32 && nx >= 0 && nx < 32);
        pn[k] = ny*32 + nx;
        aw[k] = attw[q][k];
    }
    size_t fbase = (size_t)b*HW;
    size_t obase = ((size_t)(b*1024 + 512 + (p >> 1)))*1024 + (p & 1)*512;
    #pragma unroll
    for (int j = 0; j < 4; j++) {
        int c = l16*8 + j*128;
        float g0 = 0.f, g1 = 0.f, g2 = 0.f, g3 = 0.f, g4 = 0.f, g5 = 0.f, g6 = 0.f, g7 = 0.f;
        #pragma unroll
        for (int k = 0; k < 9; k++) {
            if (valid[k]) {
                uint4 u = *(const uint4*)&g_fT[(fbase + pn[k])*CH + c];
                float2 a0 = hf2f(u.x), a1 = hf2f(u.y), a2 = hf2f(u.z), a3 = hf2f(u.w);
                float wgt = aw[k];
                g0 += wgt*a0.x; g1 += wgt*a0.y; g2 += wgt*a1.x; g3 += wgt*a1.y;
                g4 += wgt*a2.x; g5 += wgt*a2.y; g6 += wgt*a3.x; g7 += wgt*a3.y;
            }
        }
        __half2 h0 = __floats2half2_rn(g0, g1), h1 = __floats2half2_rn(g2, g3);
        __half2 h2 = __floats2half2_rn(g4, g5), h3 = __floats2half2_rn(g6, g7);
        uint4 o;
        o.x = *(uint32_t*)&h0; o.y = *(uint32_t*)&h1;
        o.z = *(uint32_t*)&h2; o.w = *(uint32_t*)&h3;
        *(uint4*)&g_Bh[obase + c] = o;
    }
}

// ---------------- down GEMM via mma.sync fp16, 3-stage pipeline ------------
__global__ void __launch_bounds__(256, 2) k_down_mma() {
    __shared__ __half As[3][128*32];
    __shared__ __half Bs[3][32*128];
    int t = threadIdx.x, lane = t & 31, wid = t >> 5;
    int m0 = blockIdx.x*128, n0 = blockIdx.y*128, b = blockIdx.z;
    int wm = (wid & 3)*32, wn = (wid >> 2)*64;
    const __half* Bb = g_Bh + (size_t)b*1024*1024;

    float acc[2][8][4];
    #pragma unroll
    for (int i = 0; i < 2; i++)
        #pragma unroll
        for (int j = 0; j < 8; j++)
            #pragma unroll
            for (int r = 0; r < 4; r++) acc[i][j][r] = 0.f;

    auto load_stage = [&](int kb, int s) {
        int kp = kb*32;
        uint32_t sa = smem_u32(&As[s][0]);
        uint32_t sb2 = smem_u32(&Bs[s][0]);
        #pragma unroll
        for (int i = 0; i < 2; i++) {
            int ch = t + i*256;
            int row = ch >> 2, c4 = ch & 3;
            cpasync16(sa + swz(row*64 + c4*16),
                      g_A + ((size_t)(m0+row)*1024 + kp + c4*8));
            int br = ch >> 4, bc = ch & 15;
            cpasync16(sb2 + br*256 + ((bc ^ (br & 7)) << 4),
                      Bb + (size_t)(kp+br)*1024 + n0 + bc*8);
        }
        cp_commit();
    };

    load_stage(0, 0);
    load_stage(1, 1);

    for (int kb = 0; kb < 32; kb++) {
        int s = kb - (kb/3)*3;
        if (kb < 31) cp_wait1(); else cp_wait0();
        __syncthreads();
        if (kb + 2 < 32) load_stage(kb+2, (kb+2) - ((kb+2)/3)*3);

        uint32_t abase = smem_u32(&As[s][0]);
        uint32_t bbase = smem_u32(&Bs[s][0]);
        int tl = lane >> 3, rw = lane & 7;
        #pragma unroll
        for (int k16 = 0; k16 < 2; k16++) {
            int k0 = k16*16;
            uint32_t bfr[4][4];
            #pragma unroll
            for (int j2 = 0; j2 < 4; j2++) {
                int krow = k0 + (tl & 1)*8 + rw;
                int ncol = wn + j2*16 + (tl >> 1)*8;
                uint32_t bd = bbase + krow*256 + ((((ncol >> 3) ^ (krow & 7)) << 4));
                asm volatile("ldmatrix.sync.aligned.m8n8.x4.trans.shared.b16 {%0,%1,%2,%3}, [%4];"
                             : "=r"(bfr[j2][0]), "=r"(bfr[j2][1]), "=r"(bfr[j2][2]), "=r"(bfr[j2][3])
                             : "r"(bd));
            }
            uint32_t af[2][4];
            #pragma unroll
            for (int i = 0; i < 2; i++) {
                int mm = wm + i*16 + (tl & 1)*8 + rw;
                int kk = k0 + (tl >> 1)*8;
                uint32_t ad = abase + swz((uint32_t)(mm*64 + kk*2));
                asm volatile("ldmatrix.sync.aligned.m8n8.x4.shared.b16 {%0,%1,%2,%3}, [%4];"
                             : "=r"(af[i][0]), "=r"(af[i][1]), "=r"(af[i][2]), "=r"(af[i][3])
                             : "r"(ad));
            }
            #pragma unroll
            for (int i = 0; i < 2; i++)
                #pragma unroll
                for (int j = 0; j < 8; j++) {
                    uint32_t b0 = bfr[j >> 1][(j & 1)*2 + 0];
                    uint32_t b1 = bfr[j >> 1][(j & 1)*2 + 1];
                    asm volatile(
                        "mma.sync.aligned.m16n8k16.row.col.f32.f16.f16.f32 "
                        "{%0,%1,%2,%3}, {%4,%5,%6,%7}, {%8,%9}, {%0,%1,%2,%3};"
                        : "+f"(acc[i][j][0]), "+f"(acc[i][j][1]),
                          "+f"(acc[i][j][2]), "+f"(acc[i][j][3])
                        : "r"(af[i][0]), "r"(af[i][1]), "r"(af[i][2]), "r"(af[i][3]),
                          "r"(b0), "r"(b1));
                }
        }
    }

    float* Cm = g_z + (size_t)b*512*1024;
    #pragma unroll
    for (int i = 0; i < 2; i++) {
        int mrow = m0 + wm + i*16 + (lane >> 2);
        #pragma unroll
        for (int j = 0; j < 8; j++) {
            int n = n0 + wn + j*8 + (lane & 3)*2;
            *(float2*)&Cm[(size_t)mrow*1024 + n]     = make_float2(acc[i][j][0], acc[i][j][1]);
            *(float2*)&Cm[(size_t)(mrow+8)*1024 + n] = make_float2(acc[i][j][2], acc[i][j][3]);
        }
    }
}

// ---------------- fused InstanceNorm + LeakyReLU (float4) ------------------
__global__ void k_finish(float* __restrict__ out) {
    int o = blockIdx.x, b = blockIdx.y, t = threadIdx.x;
    size_t base = (size_t)(b*CH + o)*HW;
    float4 v = ((const float4*)(g_z + base))[t];
    float s = v.x + v.y + v.z + v.w;
    float sq = v.x*v.x + v.y*v.y + v.z*v.z + v.w*v.w;
    #pragma unroll
    for (int o2 = 16; o2; o2 >>= 1) {
        s  += __shfl_xor_sync(~0u, s,  o2);
        sq += __shfl_xor_sync(~0u, sq, o2);
    }
    __shared__ float ws[8][2];
    __shared__ float smu, srs;
    if ((t & 31) == 0) { ws[t>>5][0] = s; ws[t>>5][1] = sq; }
    __syncthreads();
    if (t == 0) {
        float S = 0.f, Q = 0.f;
        #pragma unroll
        for (int w = 0; w < 8; w++) { S += ws[w][0]; Q += ws[w][1]; }
        float mu = S*(1.0f/HW);
        float var = Q*(1.0f/HW) - mu*mu;
        smu = mu; srs = rsqrtf(var + 1e-5f);
    }
    __syncthreads();
    float4 r;
    r.x = (v.x - smu)*srs; r.x = r.x >= 0.f ? r.x : 0.2f*r.x;
    r.y = (v.y - smu)*srs; r.y = r.y >= 0.f ? r.y : 0.2f*r.y;
    r.z = (v.z - smu)*srs; r.z = r.z >= 0.f ? r.z : 0.2f*r.z;
    r.w = (v.w - smu)*srs; r.w = r.w >= 0.f ? r.w : 0.2f*r.w;
    ((float4*)(out + base))[t] = r;
}

// ---------------- launch (serial, best-known order) -------------------------
extern "C" void kernel_launch(void* const* d_in, const int* in_sizes, int n_in,
                              void* d_out, int out_size) {
    const float* x   = (const float*)d_in[0];
    const float* w1  = (const float*)d_in[1];
    const float* b1  = (const float*)d_in[2];
    const float* w2  = (const float*)d_in[3];
    const float* b2  = (const float*)d_in[4];
    const float* dw  = (const float*)d_in[5];
    const float* gus = (const float*)d_in[6];
    float* out = (float*)d_out;

    k_pre<<<513, 1024>>>(dw, gus);
    k_se_reduce<<<dim3(CH/2, NB), 256>>>(x);
    k_se_mlp<<<NB, 512>>>(w1, b1, w2, b2);
    k_makeT<<<dim3(32, 16, NB), dim3(32, 8)>>>(x);
    k_gusA<<<dim3(32, NB), 256>>>();
    k_gusB<<<dim3(32, NB), 256>>>();
    k_attn<<<dim3(8, 8, NB), 256>>>();
    k_down_mma<<<dim3(4, 8, NB), 256>>>();
    k_finish<<<dim3(CH, NB), 256>>>(out);
}

// round 17
// speedup vs baseline: 1.0753x; 1.0122x over previous
#include <cuda_runtime.h>
#include <cuda_bf16.h>
#include <cuda_fp16.h>
#include <math.h>
#include <stdint.h>

#define NB 16
#define CH 512
#define HW 1024

// ---------------- scratch (static device globals) --------------------------
__device__ float g_ghat[32*32];
__device__ float g_s[NB*CH];
__device__ float g_ysc[NB*CH];
__device__ __half g_fT[(size_t)NB*HW*CH];
__device__ __nv_bfloat16 g_sigT[(size_t)NB*HW*CH];
__device__ __half g_w1buf[(size_t)NB*32*32*CH];
__device__ float g_z[(size_t)NB*CH*HW];
__device__ __half g_A[(size_t)512*1024];
__device__ __half g_Bh[(size_t)NB*1024*1024];

// ---------------- PTX helpers ----------------------------------------------
__device__ __forceinline__ uint32_t smem_u32(const void* p) {
    uint32_t a;
    asm("{ .reg .u64 t; cvta.to.shared.u64 t, %1; cvt.u32.u64 %0, t; }" : "=r"(a) : "l"(p));
    return a;
}
__device__ __forceinline__ void cpasync16(uint32_t saddr, const void* gaddr) {
    asm volatile("cp.async.cg.shared.global [%0], [%1], 16;" :: "r"(saddr), "l"(gaddr) : "memory");
}
__device__ __forceinline__ void cp_commit() { asm volatile("cp.async.commit_group;" ::: "memory"); }
__device__ __forceinline__ void cp_wait1() { asm volatile("cp.async.wait_group 1;" ::: "memory"); }
__device__ __forceinline__ void cp_wait0() { asm volatile("cp.async.wait_group 0;" ::: "memory"); }
__device__ __forceinline__ uint32_t swz(uint32_t x) { return x ^ ((x >> 3) & 0x70); }
__device__ __forceinline__ float2 bf2f(uint32_t u) {
    __nv_bfloat162 h = *reinterpret_cast<__nv_bfloat162*>(&u);
    return __bfloat1622float2(h);
}
__device__ __forceinline__ float2 hf2f(uint32_t u) {
    __half2 h = *reinterpret_cast<__half2*>(&u);
    return __half22float2(h);
}

// ---------------- convA + ghat (merged, one launch) -------------------------
__global__ void k_pre(const float* __restrict__ Wd, const float* __restrict__ gus) {
    if (blockIdx.x < 512) {
        int r = blockIdx.x, c = threadIdx.x;
        g_A[(size_t)r*1024 + c] = __float2half_rn(Wd[(size_t)r*1024 + c]);
    } else {
        int t = threadIdx.x;
        int i = t >> 5, y = t & 31;
        const float* p = gus + (size_t)(i*32)*1024 + y*32;
        float s = 0.f;
        #pragma unroll
        for (int x = 0; x < 32; x++) s += p[x];
        g_ghat[t] = s;
    }
}

// ---------------- SE: spatial mean (float4, 2 channels per block) ----------
__global__ void k_se_reduce(const float* __restrict__ x) {
    int t = threadIdx.x;
    int grp = t >> 7, th = t & 127;
    int c = blockIdx.x*2 + grp, b = blockIdx.y;
    const float4* p = (const float4*)(x + ((size_t)(b*CH + c))*HW);
    float s = 0.f;
    #pragma unroll
    for (int j = 0; j < 2; j++) {
        float4 v = p[th + j*128];
        s += v.x + v.y + v.z + v.w;
    }
    #pragma unroll
    for (int o = 16; o; o >>= 1) s += __shfl_xor_sync(~0u, s, o);
    __shared__ float ws[2][4];
    if ((th & 31) == 0) ws[grp][th >> 5] = s;
    __syncthreads();
    if (th == 0)
        g_s[b*CH + c] = (ws[grp][0]+ws[grp][1]+ws[grp][2]+ws[grp][3]) * (1.0f/HW);
}

// ---------------- SE: tiny MLP ---------------------------------------------
__global__ void k_se_mlp(const float* __restrict__ w1, const float* __restrict__ b1,
                         const float* __restrict__ w2, const float* __restrict__ b2) {
    int b = blockIdx.x, t = threadIdx.x;
    __shared__ float ssh[CH];
    __shared__ float hsh[32];
    ssh[t] = g_s[b*CH + t];
    __syncthreads();
    if (t < 32) {
        float a = b1[t];
        const float* w = w1 + t*CH;
        for (int c = 0; c < CH; c++) a += w[c]*ssh[c];
        hsh[t] = fmaxf(a, 0.f);
    }
    __syncthreads();
    float a = b2[t];
    const float* w = w2 + t*32;
    #pragma unroll
    for (int j = 0; j < 32; j++) a += w[j]*hsh[j];
    g_ysc[b*CH + t] = 1.f/(1.f + __expf(-a));
}

// ---------------- out32 transpose + sigmoid (fT fp16, sigT bf16) -----------
__global__ void k_makeT(const float* __restrict__ x) {
    int p0 = blockIdx.x*32, c0 = blockIdx.y*32, b = blockIdx.z;
    int tx = threadIdx.x, ty = threadIdx.y;
    __shared__ float tile[32][33];
    #pragma unroll
    for (int i = 0; i < 4; i++) {
        int c = c0 + ty + i*8;
        tile[ty+i*8][tx] = x[((size_t)(b*CH + c))*HW + p0 + tx] * g_ysc[b*CH + c];
    }
    __syncthreads();
    #pragma unroll
    for (int i = 0; i < 4; i++) {
        int p = p0 + ty + i*8;
        float v = tile[tx][ty+i*8];
        size_t idx = ((size_t)(b*HW + p))*CH + c0 + tx;
        g_fT[idx] = __float2half_rn(v);
        g_sigT[idx] = __float2bfloat16(1.f/(1.f + __expf(-v)));
    }
}

// ---------------- gus stage A (fp16 in/out, fp32 accum) --------------------
__global__ void k_gusA() {
    int y = blockIdx.x, b = blockIdx.y, t = threadIdx.x;
    __shared__ float ghT[1024];
    __shared__ float slab[32][256];
    for (int idx = t; idx < 1024; idx += 256) {
        int xx = idx >> 5, k = idx & 31;
        ghT[idx] = g_ghat[k*32 + xx];
    }
    for (int cc = 0; cc < CH; cc += 256) {
        __syncthreads();
        for (int idx = t; idx < 32*128; idx += 256) {
            int xr = idx >> 7, c2 = idx & 127;
            uint32_t u = ((const uint32_t*)(g_fT + ((size_t)(b*HW + y*32 + xr))*CH + cc))[c2];
            float2 f = hf2f(u);
            slab[xr][c2*2] = f.x; slab[xr][c2*2+1] = f.y;
        }
        __syncthreads();
        float acc[32];
        #pragma unroll
        for (int k = 0; k < 32; k++) acc[k] = 0.f;
        #pragma unroll
        for (int xx = 0; xx < 32; xx++) {
            float v = slab[xx][t];
            const float4* gp = (const float4*)&ghT[xx*32];
            #pragma unroll
            for (int q = 0; q < 8; q++) {
                float4 g4 = gp[q];
                acc[q*4+0] += g4.x*v; acc[q*4+1] += g4.y*v;
                acc[q*4+2] += g4.z*v; acc[q*4+3] += g4.w*v;
            }
        }
        #pragma unroll
        for (int k = 0; k < 32; k++)
            g_w1buf[((size_t)((b*32 + y)*32 + k))*CH + cc + t] = __float2half_rn(acc[k]);
    }
}

// ---------------- gus stage B (fp16 in) -> fp16 act ------------------------
__global__ void k_gusB() {
    int k = blockIdx.x, b = blockIdx.y, t = threadIdx.x;
    __shared__ float ghB[1024];
    __shared__ float slab[32][256];
    for (int idx = t; idx < 1024; idx += 256) {
        int yy = idx >> 5, i = idx & 31;
        ghB[idx] = g_ghat[i*32 + yy];
    }
    int half = k & 1, kr = k >> 1;
    for (int cc = 0; cc < CH; cc += 256) {
        __syncthreads();
        for (int idx = t; idx < 32*128; idx += 256) {
            int yr = idx >> 7, c2 = idx & 127;
            uint32_t u = ((const uint32_t*)(g_w1buf + ((size_t)((b*32 + yr)*32 + k))*CH + cc))[c2];
            float2 f = hf2f(u);
            slab[yr][c2*2] = f.x; slab[yr][c2*2+1] = f.y;
        }
        __syncthreads();
        float acc[32];
        #pragma unroll
        for (int i = 0; i < 32; i++) acc[i] = 0.f;
        #pragma unroll
        for (int yy = 0; yy < 32; yy++) {
            float v = slab[yy][t];
            const float4* gp = (const float4*)&ghB[yy*32];
            #pragma unroll
            for (int q = 0; q < 8; q++) {
                float4 g4 = gp[q];
                acc[q*4+0] += g4.x*v; acc[q*4+1] += g4.y*v;
                acc[q*4+2] += g4.z*v; acc[q*4+3] += g4.w*v;
            }
        }
        #pragma unroll
        for (int i = 0; i < 32; i++)
            g_Bh[((size_t)(b*1024 + i*16 + kr))*1024 + half*512 + cc + t] =
                __float2half_rn(acc[i]);
    }
}

// ---------------- 3x3 patch self-attention, 4x4 pixel tiles ----------------
__global__ void __launch_bounds__(256) k_attn() {
    __shared__ uint32_t sig2[36*256];
    __shared__ float attw[16][9];
    int tx0 = blockIdx.x*4, ty0 = blockIdx.y*4, b = blockIdx.z;
    int t = threadIdx.x, lane = t & 31, w = t >> 5;
    const uint32_t* gsig = (const uint32_t*)g_sigT + (size_t)b*HW*256;

    for (int e = t; e < 9216; e += 256) {
        int r = e >> 8, c2 = e & 255;
        int j = r/6, i = r - j*6;
        int ny = ty0 - 1 + j, nx = tx0 - 1 + i;
        uint32_t v = 0;
        if (ny >= 0 && ny < 32 && nx >= 0 && nx < 32)
            v = gsig[(size_t)(ny*32 + nx)*256 + c2];
        sig2[e] = v;
    }
    __syncthreads();

    #pragma unroll
    for (int qq = 0; qq < 2; qq++) {
        int q = w*2 + qq, py = q >> 2, px = q & 3;
        int rc = (py+1)*6 + (px+1);
        float acc[9];
        #pragma unroll
        for (int k = 0; k < 9; k++) acc[k] = 0.f;
        #pragma unroll
        for (int i = 0; i < 4; i++) {
            int c2 = lane*2 + i*64;
            uint2 ce = *(const uint2*)&sig2[rc*256 + c2];
            float2 c0 = bf2f(ce.x), c1 = bf2f(ce.y);
            #pragma unroll
            for (int k = 0; k < 9; k++) {
                int rk = rc + (k/3 - 1)*6 + (k%3 - 1);
                uint2 ne = *(const uint2*)&sig2[rk*256 + c2];
                float2 n0 = bf2f(ne.x), n1 = bf2f(ne.y);
                acc[k] += c0.x*n0.x + c0.y*n0.y + c1.x*n1.x + c1.y*n1.y;
            }
        }
        #pragma unroll
        for (int k = 0; k < 9; k++)
            #pragma unroll
            for (int o = 16; o; o >>= 1) acc[k] += __shfl_xor_sync(~0u, acc[k], o);
        float lg[9], m = -1e30f;
        #pragma unroll
        for (int k = 0; k < 9; k++) { lg[k] = acc[k]*(1.0f/CH); m = fmaxf(m, lg[k]); }
        float den = 0.f, e9[9];
        #pragma unroll
        for (int k = 0; k < 9; k++) { e9[k] = __expf(lg[k]-m); den += e9[k]; }
        float rd = 1.f/den;
        if (lane == 0) {
            #pragma unroll
            for (int k = 0; k < 9; k++) attw[q][k] = e9[k]*rd;
        }
    }
    __syncthreads();

    int q = t >> 4, l16 = t & 15;
    int py = q >> 2, px = q & 3;
    int yy0 = ty0 + py, xx0 = tx0 + px;
    int p = yy0*32 + xx0;
    float aw[9]; int pn[9]; bool valid[9];
    #pragma unroll
    for (int k = 0; k < 9; k++) {
        int dy = k/3 - 1, dx = k%3 - 1;
        int ny = yy0 + dy, nx = xx0 + dx;
        valid[k] = (ny >= 0 && ny < 32 && nx >= 0 && nx < 32);
        pn[k] = ny*32 + nx;
        aw[k] = attw[q][k];
    }
    size_t fbase = (size_t)b*HW;
    size_t obase = ((size_t)(b*1024 + 512 + (p >> 1)))*1024 + (p & 1)*512;
    #pragma unroll
    for (int j = 0; j < 4; j++) {
        int c = l16*8 + j*128;
        float g0 = 0.f, g1 = 0.f, g2 = 0.f, g3 = 0.f, g4 = 0.f, g5 = 0.f, g6 = 0.f, g7 = 0.f;
        #pragma unroll
        for (int k = 0; k < 9; k++) {
            if (valid[k]) {
                uint4 u = *(const uint4*)&g_fT[(fbase + pn[k])*CH + c];
                float2 a0 = hf2f(u.x), a1 = hf2f(u.y), a2 = hf2f(u.z), a3 = hf2f(u.w);
                float wgt = aw[k];
                g0 += wgt*a0.x; g1 += wgt*a0.y; g2 += wgt*a1.x; g3 += wgt*a1.y;
                g4 += wgt*a2.x; g5 += wgt*a2.y; g6 += wgt*a3.x; g7 += wgt*a3.y;
            }
        }
        __half2 h0 = __floats2half2_rn(g0, g1), h1 = __floats2half2_rn(g2, g3);
        __half2 h2 = __floats2half2_rn(g4, g5), h3 = __floats2half2_rn(g6, g7);
        uint4 o;
        o.x = *(uint32_t*)&h0; o.y = *(uint32_t*)&h1;
        o.z = *(uint32_t*)&h2; o.w = *(uint32_t*)&h3;
        *(uint4*)&g_Bh[obase + c] = o;
    }
}

// ---------------- down GEMM via mma.sync fp16, 3-stage pipeline ------------
__global__ void __launch_bounds__(256, 2) k_down_mma() {
    __shared__ __half As[3][128*32];
    __shared__ __half Bs[3][32*128];
    int t = threadIdx.x, lane = t & 31, wid = t >> 5;
    int m0 = blockIdx.x*128, n0 = blockIdx.y*128, b = blockIdx.z;
    int wm = (wid & 3)*32, wn = (wid >> 2)*64;
    const __half* Bb = g_Bh + (size_t)b*1024*1024;

    float acc[2][8][4];
    #pragma unroll
    for (int i = 0; i < 2; i++)
        #pragma unroll
        for (int j = 0; j < 8; j++)
            #pragma unroll
            for (int r = 0; r < 4; r++) acc[i][j][r] = 0.f;

    auto load_stage = [&](int kb, int s) {
        int kp = kb*32;
        uint32_t sa = smem_u32(&As[s][0]);
        uint32_t sb2 = smem_u32(&Bs[s][0]);
        #pragma unroll
        for (int i = 0; i < 2; i++) {
            int ch = t + i*256;
            int row = ch >> 2, c4 = ch & 3;
            cpasync16(sa + swz(row*64 + c4*16),
                      g_A + ((size_t)(m0+row)*1024 + kp + c4*8));
            int br = ch >> 4, bc = ch & 15;
            cpasync16(sb2 + br*256 + ((bc ^ (br & 7)) << 4),
                      Bb + (size_t)(kp+br)*1024 + n0 + bc*8);
        }
        cp_commit();
    };

    load_stage(0, 0);
    load_stage(1, 1);

    for (int kb = 0; kb < 32; kb++) {
        int s = kb - (kb/3)*3;
        if (kb < 31) cp_wait1(); else cp_wait0();
        __syncthreads();
        if (kb + 2 < 32) load_stage(kb+2, (kb+2) - ((kb+2)/3)*3);

        uint32_t abase = smem_u32(&As[s][0]);
        uint32_t bbase = smem_u32(&Bs[s][0]);
        int tl = lane >> 3, rw = lane & 7;
        #pragma unroll
        for (int k16 = 0; k16 < 2; k16++) {
            int k0 = k16*16;
            uint32_t bfr[4][4];
            #pragma unroll
            for (int j2 = 0; j2 < 4; j2++) {
                int krow = k0 + (tl & 1)*8 + rw;
                int ncol = wn + j2*16 + (tl >> 1)*8;
                uint32_t bd = bbase + krow*256 + ((((ncol >> 3) ^ (krow & 7)) << 4));
                asm volatile("ldmatrix.sync.aligned.m8n8.x4.trans.shared.b16 {%0,%1,%2,%3}, [%4];"
                             : "=r"(bfr[j2][0]), "=r"(bfr[j2][1]), "=r"(bfr[j2][2]), "=r"(bfr[j2][3])
                             : "r"(bd));
            }
            uint32_t af[2][4];
            #pragma unroll
            for (int i = 0; i < 2; i++) {
                int mm = wm + i*16 + (tl & 1)*8 + rw;
                int kk = k0 + (tl >> 1)*8;
                uint32_t ad = abase + swz((uint32_t)(mm*64 + kk*2));
                asm volatile("ldmatrix.sync.aligned.m8n8.x4.shared.b16 {%0,%1,%2,%3}, [%4];"
                             : "=r"(af[i][0]), "=r"(af[i][1]), "=r"(af[i][2]), "=r"(af[i][3])
                             : "r"(ad));
            }
            #pragma unroll
            for (int i = 0; i < 2; i++)
                #pragma unroll
                for (int j = 0; j < 8; j++) {
                    uint32_t b0 = bfr[j >> 1][(j & 1)*2 + 0];
                    uint32_t b1 = bfr[j >> 1][(j & 1)*2 + 1];
                    asm volatile(
                        "mma.sync.aligned.m16n8k16.row.col.f32.f16.f16.f32 "
                        "{%0,%1,%2,%3}, {%4,%5,%6,%7}, {%8,%9}, {%0,%1,%2,%3};"
                        : "+f"(acc[i][j][0]), "+f"(acc[i][j][1]),
                          "+f"(acc[i][j][2]), "+f"(acc[i][j][3])
                        : "r"(af[i][0]), "r"(af[i][1]), "r"(af[i][2]), "r"(af[i][3]),
                          "r"(b0), "r"(b1));
                }
        }
    }

    float* Cm = g_z + (size_t)b*512*1024;
    #pragma unroll
    for (int i = 0; i < 2; i++) {
        int mrow = m0 + wm + i*16 + (lane >> 2);
        #pragma unroll
        for (int j = 0; j < 8; j++) {
            int n = n0 + wn + j*8 + (lane & 3)*2;
            *(float2*)&Cm[(size_t)mrow*1024 + n]     = make_float2(acc[i][j][0], acc[i][j][1]);
            *(float2*)&Cm[(size_t)(mrow+8)*1024 + n] = make_float2(acc[i][j][2], acc[i][j][3]);
        }
    }
}

// ---------------- fused InstanceNorm + LeakyReLU (2 channels/block) --------
__global__ void k_finish(float* __restrict__ out) {
    int t = threadIdx.x;                 // 256 = 2 groups of 128
    int grp = t >> 7, th = t & 127;
    int o = blockIdx.x*2 + grp, b = blockIdx.y;
    size_t base = (size_t)(b*CH + o)*HW;
    const float4* zp = (const float4*)(g_z + base);
    float4 v0 = zp[th], v1 = zp[th + 128];
    float s  = v0.x + v0.y + v0.z + v0.w + v1.x + v1.y + v1.z + v1.w;
    float sq = v0.x*v0.x + v0.y*v0.y + v0.z*v0.z + v0.w*v0.w
             + v1.x*v1.x + v1.y*v1.y + v1.z*v1.z + v1.w*v1.w;
    #pragma unroll
    for (int o2 = 16; o2; o2 >>= 1) {
        s  += __shfl_xor_sync(~0u, s,  o2);
        sq += __shfl_xor_sync(~0u, sq, o2);
    }
    __shared__ float ws[2][4][2];
    __shared__ float smu[2], srs[2];
    if ((th & 31) == 0) { ws[grp][th>>5][0] = s; ws[grp][th>>5][1] = sq; }
    __syncthreads();
    if (th == 0) {
        float S = 0.f, Q = 0.f;
        #pragma unroll
        for (int w = 0; w < 4; w++) { S += ws[grp][w][0]; Q += ws[grp][w][1]; }
        float mu = S*(1.0f/HW);
        float var = Q*(1.0f/HW) - mu*mu;
        smu[grp] = mu; srs[grp] = rsqrtf(var + 1e-5f);
    }
    __syncthreads();
    float mu = smu[grp], rs = srs[grp];
    float4* op = (float4*)(out + base);
    float4 r0, r1;
    r0.x = (v0.x - mu)*rs; r0.x = r0.x >= 0.f ? r0.x : 0.2f*r0.x;
    r0.y = (v0.y - mu)*rs; r0.y = r0.y >= 0.f ? r0.y : 0.2f*r0.y;
    r0.z = (v0.z - mu)*rs; r0.z = r0.z >= 0.f ? r0.z : 0.2f*r0.z;
    r0.w = (v0.w - mu)*rs; r0.w = r0.w >= 0.f ? r0.w : 0.2f*r0.w;
    r1.x = (v1.x - mu)*rs; r1.x = r1.x >= 0.f ? r1.x : 0.2f*r1.x;
    r1.y = (v1.y - mu)*rs; r1.y = r1.y >= 0.f ? r1.y : 0.2f*r1.y;
    r1.z = (v1.z - mu)*rs; r1.z = r1.z >= 0.f ? r1.z : 0.2f*r1.z;
    r1.w = (v1.w - mu)*rs; r1.w = r1.w >= 0.f ? r1.w : 0.2f*r1.w;
    op[th] = r0;
    op[th + 128] = r1;
}

// ---------------- launch (serial, best-known order) -------------------------
extern "C" void kernel_launch(void* const* d_in, const int* in_sizes, int n_in,
                              void* d_out, int out_size) {
    const float* x   = (const float*)d_in[0];
    const float* w1  = (const float*)d_in[1];
    const float* b1  = (const float*)d_in[2];
    const float* w2  = (const float*)d_in[3];
    const float* b2  = (const float*)d_in[4];
    const float* dw  = (const float*)d_in[5];
    const float* gus = (const float*)d_in[6];
    float* out = (float*)d_out;

    k_pre<<<513, 1024>>>(dw, gus);
    k_se_reduce<<<dim3(CH/2, NB), 256>>>(x);
    k_se_mlp<<<NB, 512>>>(w1, b1, w2, b2);
    k_makeT<<<dim3(32, 16, NB), dim3(32, 8)>>>(x);
    k_gusA<<<dim3(32, NB), 256>>>();
    k_gusB<<<dim3(32, NB), 256>>>();
    k_attn<<<dim3(8, 8, NB), 256>>>();
    k_down_mma<<<dim3(4, 8, NB), 256>>>();
    k_finish<<<dim3(CH/2, NB), 256>>>(out);
}